// round 13
// baseline (speedup 1.0000x reference)
#include <cuda_runtime.h>
#include <cuda_fp16.h>
#include <cstdint>
#include <cfloat>

#define N_ROWS   262144
#define K_CENT   256
#define D_DIM    64
#define NUM_CLS  10
#define N_GROUPS (N_ROWS / 16)       /* 16384 16-row groups */
#define GRID_X   444                 /* 3 CTAs/SM * 148 SMs */
#define NTHREADS 192                 /* 6 warps/CTA -> 4.5 warps/SMSP */
#define TOT_WARPS (GRID_X * 6)       /* 2664 */

// ---------------- device-global scratch (zero at module load; last CTA re-zeros) --
__device__ double g_loss;                       // = 0.0
__device__ int    g_counts[NUM_CLS * NUM_CLS];  // = {0}
__device__ unsigned int g_done;                 // = 0

// ---------------- helpers ----------------
__device__ __forceinline__ uint32_t h2(float a, float b) {
    __half2 h = __floats2half2_rn(a, b);
    return *reinterpret_cast<uint32_t*>(&h);
}

__device__ __forceinline__ void mma_f16(float& d0, float& d1, float& d2, float& d3,
                                        uint32_t a0, uint32_t a1, uint32_t a2, uint32_t a3,
                                        uint32_t b0, uint32_t b1) {
    asm("mma.sync.aligned.m16n8k16.row.col.f32.f16.f16.f32 "
        "{%0,%1,%2,%3}, {%4,%5,%6,%7}, {%8,%9}, {%0,%1,%2,%3};"
        : "+f"(d0), "+f"(d1), "+f"(d2), "+f"(d3)
        : "r"(a0), "r"(a1), "r"(a2), "r"(a3), "r"(b0), "r"(b1));
}

// argmin key: truncate e mantissa low bits, pack col into low byte (ties -> lower col)
__device__ __forceinline__ uint32_t akey(float e, int col) {
    return (__float_as_uint(e) & 0xFFFFFF00u) | (uint32_t)col;
}

// k-permutation: within each 16-wide k-chunk, mma slot pairs of thread t4
// ({2t4,2t4+1} and {2t4+8,2t4+9}) hold global elements {4t4..4t4+3}.
// smem: per center n, 8 uint4 units. unit u=(kcp*4+t4)^((n&1)<<2) holds
// B' = -2*c fragments for k-chunks 2*kcp, 2*kcp+1. Conflict-free LDS.128.
struct SmemLayout {
    uint4 B[K_CENT * 8];    // 32 KB
    float c2[K_CENT];       // c2[n] + 1  (the "+1" of 1+d folded in)
};

__global__ __launch_bounds__(NTHREADS, 3)
void kmeans_hmma_kernel(const float* __restrict__ x,
                        const int*   __restrict__ y32,
                        const float* __restrict__ centers,
                        float* __restrict__ out) {
    extern __shared__ unsigned char s_raw[];
    SmemLayout* sm = reinterpret_cast<SmemLayout*>(s_raw);
    __shared__ int    s_hist[NUM_CLS * NUM_CLS];
    __shared__ double s_loss;
    __shared__ int    s_y_is32;
    __shared__ int    s_is_last;

    const int tid  = threadIdx.x;
    const int wid  = tid >> 5;
    const int lane = tid & 31;
    const int g    = lane >> 2;   // row within mma row-group (0..7)
    const int t4   = lane & 3;

    if (tid < NUM_CLS * NUM_CLS) s_hist[tid] = 0;
    if (tid == 0) s_loss = 0.0;
    // label dtype probe: int64 LE -> odd 32-bit words are all 0
    if (wid == 0) {
        int v = (y32[2 * (lane * 7 + 1) + 1] != 0) | (y32[2 * (lane + 64) + 1] != 0);
        uint32_t any = __ballot_sync(0xFFFFFFFFu, v);
        if (lane == 0) s_y_is32 = (any != 0);
    }

    // ---- build fp16 B' = -2*c fragments in smem (permuted k-order), once per CTA --
    for (int w = tid; w < K_CENT * 8; w += NTHREADS) {
        int n   = w >> 3;
        int u8  = w & 7;
        int kcp = u8 >> 2, tt = u8 & 3;
        const float* cn = centers + n * D_DIM;
        float4 v0 = *(const float4*)(cn + kcp * 32 + tt * 4);        // chunk 2kcp
        float4 v1 = *(const float4*)(cn + kcp * 32 + 16 + tt * 4);   // chunk 2kcp+1
        int u = u8 ^ ((n & 1) << 2);
        sm->B[n * 8 + u] = make_uint4(h2(-2.f * v0.x, -2.f * v0.y),
                                      h2(-2.f * v0.z, -2.f * v0.w),
                                      h2(-2.f * v1.x, -2.f * v1.y),
                                      h2(-2.f * v1.z, -2.f * v1.w));
    }
    // center norms + 1 (fp32 exact)
    for (int n = tid; n < K_CENT; n += NTHREADS) {
        const float4* cp = (const float4*)(centers + n * D_DIM);
        float a = 0.f;
        #pragma unroll
        for (int j = 0; j < 16; j++) {
            float4 v = cp[j];
            a = fmaf(v.x, v.x, a); a = fmaf(v.y, v.y, a);
            a = fmaf(v.z, v.z, a); a = fmaf(v.w, v.w, a);
        }
        sm->c2[n] = a + 1.0f;
    }
    __syncthreads();
    const int y_is32 = s_y_is32;

    const uint4* Bbase = sm->B + g * 8;
    const int    uswz  = (g & 1) << 2;

    float loss_local = 0.f;

    // warp-persistent distribution over 16-row groups
    for (int G = blockIdx.x * 6 + wid; G < N_GROUPS; G += TOT_WARPS) {
        const int r0 = G * 16 + g;   // rows r0, r0+8
        const float* xr0 = x + (size_t)r0 * D_DIM + t4 * 4;
        const float* xr1 = xr0 + 8 * D_DIM;

        // ---- fp16 A fragments via ONE float4 per (row, k-chunk) + row norms ----
        uint32_t ah[4][4];
        float x2a = 0.f, x2b = 0.f;
        #pragma unroll
        for (int kc = 0; kc < 4; kc++) {
            float4 va = *(const float4*)(xr0 + kc * 16);
            float4 vb = *(const float4*)(xr1 + kc * 16);
            x2a = fmaf(va.x, va.x, x2a); x2a = fmaf(va.y, va.y, x2a);
            x2a = fmaf(va.z, va.z, x2a); x2a = fmaf(va.w, va.w, x2a);
            x2b = fmaf(vb.x, vb.x, x2b); x2b = fmaf(vb.y, vb.y, x2b);
            x2b = fmaf(vb.z, vb.z, x2b); x2b = fmaf(vb.w, vb.w, x2b);
            ah[kc][0] = h2(va.x, va.y);
            ah[kc][1] = h2(vb.x, vb.y);
            ah[kc][2] = h2(va.z, va.w);
            ah[kc][3] = h2(vb.z, vb.w);
        }
        x2a += __shfl_xor_sync(0xFFFFFFFFu, x2a, 1);
        x2a += __shfl_xor_sync(0xFFFFFFFFu, x2a, 2);
        x2b += __shfl_xor_sync(0xFFFFFFFFu, x2b, 1);
        x2b += __shfl_xor_sync(0xFFFFFFFFu, x2b, 2);

        float sw0 = 0.f, swe0 = 0.f, sw1 = 0.f, swe1 = 0.f;
        float dmin0 = FLT_MAX, dmin1 = FLT_MAX;
        float dmin10_0 = FLT_MAX, dmin10_1 = FLT_MAX;
        uint32_t key10_0 = 0xFFFFFFFFu, key10_1 = 0xFFFFFFFFu;

        // acc init = (x2 + c2 + 1); B' = -2c  =>  accumulator ends as e = 1 + d
        auto body = [&](int ng, bool track10) {
            const uint4* Bn = Bbase + ng * 64;
            uint4 bv0 = Bn[(0 + t4) ^ uswz];     // k-chunks 0,1
            uint4 bv1 = Bn[(4 + t4) ^ uswz];     // k-chunks 2,3
            float2 c2p = *(const float2*)(sm->c2 + ng * 8 + t4 * 2);
            float a0 = x2a + c2p.x, a1 = x2a + c2p.y;
            float a2 = x2b + c2p.x, a3 = x2b + c2p.y;
            mma_f16(a0, a1, a2, a3, ah[0][0], ah[0][1], ah[0][2], ah[0][3], bv0.x, bv0.y);
            mma_f16(a0, a1, a2, a3, ah[1][0], ah[1][1], ah[1][2], ah[1][3], bv0.z, bv0.w);
            mma_f16(a0, a1, a2, a3, ah[2][0], ah[2][1], ah[2][2], ah[2][3], bv1.x, bv1.y);
            mma_f16(a0, a1, a2, a3, ah[3][0], ah[3][1], ah[3][2], ah[3][3], bv1.z, bv1.w);
            float w0 = __powf(a0, -0.1f);
            float w1 = __powf(a1, -0.1f);
            float w2 = __powf(a2, -0.1f);
            float w3 = __powf(a3, -0.1f);
            sw0 += w0 + w1;
            sw1 += w2 + w3;
            swe0 = fmaf(w0, a0, swe0); swe0 = fmaf(w1, a1, swe0);
            swe1 = fmaf(w2, a2, swe1); swe1 = fmaf(w3, a3, swe1);
            dmin0 = fminf(dmin0, fminf(a0, a1));
            dmin1 = fminf(dmin1, fminf(a2, a3));
            if (track10) {
                // cols < 10 live only in ng=0 (cols 0-7) and ng=1/t4==0 (cols 8,9)
                if (ng == 0 || t4 == 0) {
                    const int cb = ng * 8 + t4 * 2;
                    key10_0 = min(key10_0, min(akey(a0, cb), akey(a1, cb + 1)));
                    key10_1 = min(key10_1, min(akey(a2, cb), akey(a3, cb + 1)));
                    dmin10_0 = fminf(dmin10_0, fminf(a0, a1));
                    dmin10_1 = fminf(dmin10_1, fminf(a2, a3));
                }
            }
        };
        body(0, true);
        body(1, true);
        #pragma unroll 6
        for (int ng = 2; ng < 32; ng++) body(ng, false);

        // quad reduction (4 lanes cover all 256 cols of rows r0, r0+8)
        #pragma unroll
        for (int off = 1; off <= 2; off <<= 1) {
            sw0  += __shfl_xor_sync(0xFFFFFFFFu, sw0,  off);
            swe0 += __shfl_xor_sync(0xFFFFFFFFu, swe0, off);
            sw1  += __shfl_xor_sync(0xFFFFFFFFu, sw1,  off);
            swe1 += __shfl_xor_sync(0xFFFFFFFFu, swe1, off);
            dmin0 = fminf(dmin0, __shfl_xor_sync(0xFFFFFFFFu, dmin0, off));
            dmin1 = fminf(dmin1, __shfl_xor_sync(0xFFFFFFFFu, dmin1, off));
            dmin10_0 = fminf(dmin10_0, __shfl_xor_sync(0xFFFFFFFFu, dmin10_0, off));
            dmin10_1 = fminf(dmin10_1, __shfl_xor_sync(0xFFFFFFFFu, dmin10_1, off));
            key10_0 = min(key10_0, __shfl_xor_sync(0xFFFFFFFFu, key10_0, off));
            key10_1 = min(key10_1, __shfl_xor_sync(0xFFFFFFFFu, key10_1, off));
        }

        if (t4 == 0) {
            loss_local += swe0 / sw0 + swe1 / sw1 - 2.0f;   // swe/sw - 1 per row
            // argmin < 10  <=>  min over cols<10 equals global min (ties -> lower col)
            if (dmin10_0 <= dmin0) {
                int lab = y_is32 ? y32[r0] : y32[2 * r0];
                atomicAdd_block(&s_hist[(int)(key10_0 & 0xFFu) * NUM_CLS + lab], 1);
            }
            if (dmin10_1 <= dmin1) {
                int r1 = r0 + 8;
                int lab = y_is32 ? y32[r1] : y32[2 * r1];
                atomicAdd_block(&s_hist[(int)(key10_1 & 0xFFu) * NUM_CLS + lab], 1);
            }
        }
    }

    // ---- flush per-CTA accumulators to global ----
    #pragma unroll
    for (int off = 16; off > 0; off >>= 1)
        loss_local += __shfl_xor_sync(0xFFFFFFFFu, loss_local, off);
    if (lane == 0) atomicAdd_block(&s_loss, (double)loss_local);
    __syncthreads();
    if (tid == 0) atomicAdd(&g_loss, s_loss);
    if (tid < NUM_CLS * NUM_CLS && s_hist[tid] > 0)
        atomicAdd(&g_counts[tid], s_hist[tid]);

    // ---- last-CTA fused finalize ----
    __threadfence();
    __syncthreads();
    if (tid == 0) {
        unsigned int prev = atomicAdd(&g_done, 1u);
        s_is_last = (prev == GRID_X - 1);
    }
    __syncthreads();
    if (!s_is_last || tid != 0) return;

    float counts[NUM_CLS * NUM_CLS];
    #pragma unroll
    for (int i = 0; i < NUM_CLS * NUM_CLS; i++)
        counts[i] = (float)atomicAdd(&g_counts[i], 0);

    bool used[NUM_CLS];
    #pragma unroll
    for (int i = 0; i < NUM_CLS; i++) used[i] = false;

    float correct = 0.f;
    for (int i = 0; i < NUM_CLS; i++) {
        const float* bin = &counts[i * NUM_CLS];
        float tot = 0.f;
        for (int j = 0; j < NUM_CLS; j++) tot += bin[j];
        int label = 0; float best = bin[0];
        for (int j = 1; j < NUM_CLS; j++)
            if (bin[j] > best) { best = bin[j]; label = j; }
        if (used[label]) {
            int l2 = 0; float b2 = used[0] ? 0.f : bin[0];
            for (int j = 1; j < NUM_CLS; j++) {
                float v = used[j] ? 0.f : bin[j];
                if (v > b2) { b2 = v; l2 = j; }
            }
            label = l2;
        }
        if (tot > 0.f) { correct += bin[label]; used[label] = true; }
    }
    out[0] = (float)g_loss;
    out[1] = correct / (float)N_ROWS;

    // reset globals so the next graph replay starts from a clean state
    g_loss = 0.0;
    #pragma unroll
    for (int i = 0; i < NUM_CLS * NUM_CLS; i++) g_counts[i] = 0;
    g_done = 0u;
}

// ---------------- launch ----------------
extern "C" void kernel_launch(void* const* d_in, const int* in_sizes, int n_in,
                              void* d_out, int out_size) {
    const float* x       = (const float*)d_in[0];
    const int*   y32     = (const int*)d_in[1];
    const float* centers = (const float*)d_in[2];

    const int dyn_smem = (int)sizeof(SmemLayout);
    cudaFuncSetAttribute(kmeans_hmma_kernel,
                         cudaFuncAttributeMaxDynamicSharedMemorySize, dyn_smem);

    kmeans_hmma_kernel<<<GRID_X, NTHREADS, dyn_smem>>>(x, y32, centers, (float*)d_out);
}

// round 14
// speedup vs baseline: 1.1362x; 1.1362x over previous
#include <cuda_runtime.h>
#include <cuda_fp16.h>
#include <cstdint>
#include <cfloat>

#define N_ROWS   262144
#define K_CENT   256
#define D_DIM    64
#define NUM_CLS  10
#define TILE_M   128
#define N_TILES  (N_ROWS / TILE_M)   /* 2048 */
#define GRID_X   296                 /* 2 CTAs/SM * 148 SMs */
#define NTHREADS 256

// ---------------- device-global scratch (zero at module load; last CTA re-zeros) --
__device__ double g_loss;                       // = 0.0
__device__ int    g_counts[NUM_CLS * NUM_CLS];  // = {0}
__device__ unsigned int g_done;                 // = 0

// ---------------- helpers ----------------
__device__ __forceinline__ uint32_t h2(float a, float b) {
    __half2 h = __floats2half2_rn(a, b);
    return *reinterpret_cast<uint32_t*>(&h);
}

__device__ __forceinline__ void mma_f16(float& d0, float& d1, float& d2, float& d3,
                                        uint32_t a0, uint32_t a1, uint32_t a2, uint32_t a3,
                                        uint32_t b0, uint32_t b1) {
    asm("mma.sync.aligned.m16n8k16.row.col.f32.f16.f16.f32 "
        "{%0,%1,%2,%3}, {%4,%5,%6,%7}, {%8,%9}, {%0,%1,%2,%3};"
        : "+f"(d0), "+f"(d1), "+f"(d2), "+f"(d3)
        : "r"(a0), "r"(a1), "r"(a2), "r"(a3), "r"(b0), "r"(b1));
}

// argmin key: truncate e mantissa low bits, pack col into low byte (ties -> lower col)
__device__ __forceinline__ uint32_t akey(float e, int col) {
    return (__float_as_uint(e) & 0xFFFFFF00u) | (uint32_t)col;
}

// k-permutation: within each 16-wide k-chunk, mma slot pairs of thread t4
// ({2t4,2t4+1} and {2t4+8,2t4+9}) hold global elements {4t4..4t4+3}.
// smem: per center n, 8 uint4 units. unit u=(kcp*4+t4)^((n&1)<<2) holds
// B' = -2*c fragments for k-chunks 2*kcp, 2*kcp+1. Conflict-free LDS.128.
struct SmemLayout {
    uint4 B[K_CENT * 8];    // 32 KB
    float c2[K_CENT];       // c2[n] + 1  (the "+1" of 1+d folded in)
};

__global__ __launch_bounds__(NTHREADS, 2)
void kmeans_hmma_kernel(const float* __restrict__ x,
                        const int*   __restrict__ y32,
                        const float* __restrict__ centers,
                        float* __restrict__ out) {
    extern __shared__ unsigned char s_raw[];
    SmemLayout* sm = reinterpret_cast<SmemLayout*>(s_raw);
    __shared__ int    s_hist[NUM_CLS * NUM_CLS];
    __shared__ double s_loss;
    __shared__ int    s_y_is32;
    __shared__ int    s_is_last;

    const int tid  = threadIdx.x;
    const int wid  = tid >> 5;
    const int lane = tid & 31;
    const int g    = lane >> 2;   // row within mma row-group (0..7)
    const int t4   = lane & 3;

    if (tid < NUM_CLS * NUM_CLS) s_hist[tid] = 0;
    if (tid == 0) s_loss = 0.0;
    // label dtype probe: int64 LE -> odd 32-bit words are all 0
    if (wid == 0) {
        int v = (y32[2 * (lane * 7 + 1) + 1] != 0) | (y32[2 * (lane + 64) + 1] != 0);
        uint32_t any = __ballot_sync(0xFFFFFFFFu, v);
        if (lane == 0) s_y_is32 = (any != 0);
    }

    // ---- build fp16 B' = -2*c fragments in smem (permuted k-order), once per CTA --
    for (int w = tid; w < K_CENT * 8; w += NTHREADS) {
        int n   = w >> 3;
        int u8  = w & 7;
        int kcp = u8 >> 2, tt = u8 & 3;
        const float* cn = centers + n * D_DIM;
        float4 v0 = *(const float4*)(cn + kcp * 32 + tt * 4);        // chunk 2kcp
        float4 v1 = *(const float4*)(cn + kcp * 32 + 16 + tt * 4);   // chunk 2kcp+1
        int u = u8 ^ ((n & 1) << 2);
        sm->B[n * 8 + u] = make_uint4(h2(-2.f * v0.x, -2.f * v0.y),
                                      h2(-2.f * v0.z, -2.f * v0.w),
                                      h2(-2.f * v1.x, -2.f * v1.y),
                                      h2(-2.f * v1.z, -2.f * v1.w));
    }
    // center norms + 1 (fp32 exact)
    if (tid < K_CENT) {
        const float4* cp = (const float4*)(centers + tid * D_DIM);
        float a = 0.f;
        #pragma unroll
        for (int j = 0; j < 16; j++) {
            float4 v = cp[j];
            a = fmaf(v.x, v.x, a); a = fmaf(v.y, v.y, a);
            a = fmaf(v.z, v.z, a); a = fmaf(v.w, v.w, a);
        }
        sm->c2[tid] = a + 1.0f;
    }
    __syncthreads();
    const int y_is32 = s_y_is32;

    const uint4* Bbase = sm->B + g * 8;
    const int    uswz  = (g & 1) << 2;
    // hoisted swizzled unit indices (loop-invariant): (0+t4)^uswz and (4+t4)^uswz
    const int u0 = t4 ^ uswz;
    const int u1 = u0 ^ 4;

    float loss_local = 0.f;

    for (int t = blockIdx.x; t < N_TILES; t += GRID_X) {
        const int r0 = t * TILE_M + wid * 16 + g;   // rows r0, r0+8
        const float* xr0 = x + (size_t)r0 * D_DIM + t4 * 4;
        const float* xr1 = xr0 + 8 * D_DIM;

        // ---- fp16 A fragments via ONE float4 per (row, k-chunk) + row norms ----
        uint32_t ah[4][4];
        float x2a = 0.f, x2b = 0.f;
        #pragma unroll
        for (int kc = 0; kc < 4; kc++) {
            float4 va = *(const float4*)(xr0 + kc * 16);
            float4 vb = *(const float4*)(xr1 + kc * 16);
            x2a = fmaf(va.x, va.x, x2a); x2a = fmaf(va.y, va.y, x2a);
            x2a = fmaf(va.z, va.z, x2a); x2a = fmaf(va.w, va.w, x2a);
            x2b = fmaf(vb.x, vb.x, x2b); x2b = fmaf(vb.y, vb.y, x2b);
            x2b = fmaf(vb.z, vb.z, x2b); x2b = fmaf(vb.w, vb.w, x2b);
            ah[kc][0] = h2(va.x, va.y);   // row r0, slots 2t4,2t4+1
            ah[kc][1] = h2(vb.x, vb.y);   // row r1, slots 2t4,2t4+1
            ah[kc][2] = h2(va.z, va.w);   // row r0, slots 2t4+8,2t4+9
            ah[kc][3] = h2(vb.z, vb.w);   // row r1, slots 2t4+8,2t4+9
        }
        x2a += __shfl_xor_sync(0xFFFFFFFFu, x2a, 1);
        x2a += __shfl_xor_sync(0xFFFFFFFFu, x2a, 2);
        x2b += __shfl_xor_sync(0xFFFFFFFFu, x2b, 1);
        x2b += __shfl_xor_sync(0xFFFFFFFFu, x2b, 2);

        float sw0 = 0.f, swe0 = 0.f, sw1 = 0.f, swe1 = 0.f;
        float dmin0 = FLT_MAX, dmin1 = FLT_MAX;
        float dmin10_0 = FLT_MAX, dmin10_1 = FLT_MAX;
        uint32_t key10_0 = 0xFFFFFFFFu, key10_1 = 0xFFFFFFFFu;

        // acc init = (x2 + c2 + 1); B' = -2c  =>  accumulator ends as e = 1 + d
        auto body = [&](int ng, bool track10) {
            const uint4* Bn = Bbase + ng * 64;
            uint4 bv0 = Bn[u0];                  // k-chunks 0,1
            uint4 bv1 = Bn[u1];                  // k-chunks 2,3
            float2 c2p = *(const float2*)(sm->c2 + ng * 8 + t4 * 2);
            float a0 = x2a + c2p.x, a1 = x2a + c2p.y;
            float a2 = x2b + c2p.x, a3 = x2b + c2p.y;
            mma_f16(a0, a1, a2, a3, ah[0][0], ah[0][1], ah[0][2], ah[0][3], bv0.x, bv0.y);
            mma_f16(a0, a1, a2, a3, ah[1][0], ah[1][1], ah[1][2], ah[1][3], bv0.z, bv0.w);
            mma_f16(a0, a1, a2, a3, ah[2][0], ah[2][1], ah[2][2], ah[2][3], bv1.x, bv1.y);
            mma_f16(a0, a1, a2, a3, ah[3][0], ah[3][1], ah[3][2], ah[3][3], bv1.z, bv1.w);
            float w0 = __powf(a0, -0.1f);
            float w1 = __powf(a1, -0.1f);
            float w2 = __powf(a2, -0.1f);
            float w3 = __powf(a3, -0.1f);
            sw0 += w0 + w1;
            sw1 += w2 + w3;
            swe0 = fmaf(w0, a0, swe0); swe0 = fmaf(w1, a1, swe0);
            swe1 = fmaf(w2, a2, swe1); swe1 = fmaf(w3, a3, swe1);
            dmin0 = fminf(dmin0, fminf(a0, a1));
            dmin1 = fminf(dmin1, fminf(a2, a3));
            if (track10) {
                // cols < 10 live only in ng=0 (cols 0-7) and ng=1/t4==0 (cols 8,9)
                if (ng == 0 || t4 == 0) {
                    const int cb = ng * 8 + t4 * 2;
                    key10_0 = min(key10_0, min(akey(a0, cb), akey(a1, cb + 1)));
                    key10_1 = min(key10_1, min(akey(a2, cb), akey(a3, cb + 1)));
                    dmin10_0 = fminf(dmin10_0, fminf(a0, a1));
                    dmin10_1 = fminf(dmin10_1, fminf(a2, a3));
                }
            }
        };
        body(0, true);
        body(1, true);
        #pragma unroll 10
        for (int ng = 2; ng < 32; ng++) body(ng, false);

        // quad reduction (4 lanes cover all 256 cols of rows r0, r0+8)
        #pragma unroll
        for (int off = 1; off <= 2; off <<= 1) {
            sw0  += __shfl_xor_sync(0xFFFFFFFFu, sw0,  off);
            swe0 += __shfl_xor_sync(0xFFFFFFFFu, swe0, off);
            sw1  += __shfl_xor_sync(0xFFFFFFFFu, sw1,  off);
            swe1 += __shfl_xor_sync(0xFFFFFFFFu, swe1, off);
            dmin0 = fminf(dmin0, __shfl_xor_sync(0xFFFFFFFFu, dmin0, off));
            dmin1 = fminf(dmin1, __shfl_xor_sync(0xFFFFFFFFu, dmin1, off));
            dmin10_0 = fminf(dmin10_0, __shfl_xor_sync(0xFFFFFFFFu, dmin10_0, off));
            dmin10_1 = fminf(dmin10_1, __shfl_xor_sync(0xFFFFFFFFu, dmin10_1, off));
            key10_0 = min(key10_0, __shfl_xor_sync(0xFFFFFFFFu, key10_0, off));
            key10_1 = min(key10_1, __shfl_xor_sync(0xFFFFFFFFu, key10_1, off));
        }

        if (t4 == 0) {
            loss_local += swe0 / sw0 + swe1 / sw1 - 2.0f;   // swe/sw - 1 per row
            // argmin < 10  <=>  min over cols<10 equals global min (ties -> lower col)
            if (dmin10_0 <= dmin0) {
                int lab = y_is32 ? y32[r0] : y32[2 * r0];
                atomicAdd_block(&s_hist[(int)(key10_0 & 0xFFu) * NUM_CLS + lab], 1);
            }
            if (dmin10_1 <= dmin1) {
                int r1 = r0 + 8;
                int lab = y_is32 ? y32[r1] : y32[2 * r1];
                atomicAdd_block(&s_hist[(int)(key10_1 & 0xFFu) * NUM_CLS + lab], 1);
            }
        }
    }

    // ---- flush per-CTA accumulators to global ----
    #pragma unroll
    for (int off = 16; off > 0; off >>= 1)
        loss_local += __shfl_xor_sync(0xFFFFFFFFu, loss_local, off);
    if (lane == 0) atomicAdd_block(&s_loss, (double)loss_local);
    __syncthreads();
    if (tid == 0) atomicAdd(&g_loss, s_loss);
    if (tid < NUM_CLS * NUM_CLS && s_hist[tid] > 0)
        atomicAdd(&g_counts[tid], s_hist[tid]);

    // ---- last-CTA fused finalize ----
    __threadfence();
    __syncthreads();
    if (tid == 0) {
        unsigned int prev = atomicAdd(&g_done, 1u);
        s_is_last = (prev == GRID_X - 1);
    }
    __syncthreads();
    if (!s_is_last || tid != 0) return;

    float counts[NUM_CLS * NUM_CLS];
    #pragma unroll
    for (int i = 0; i < NUM_CLS * NUM_CLS; i++)
        counts[i] = (float)atomicAdd(&g_counts[i], 0);

    bool used[NUM_CLS];
    #pragma unroll
    for (int i = 0; i < NUM_CLS; i++) used[i] = false;

    float correct = 0.f;
    for (int i = 0; i < NUM_CLS; i++) {
        const float* bin = &counts[i * NUM_CLS];
        float tot = 0.f;
        for (int j = 0; j < NUM_CLS; j++) tot += bin[j];
        int label = 0; float best = bin[0];
        for (int j = 1; j < NUM_CLS; j++)
            if (bin[j] > best) { best = bin[j]; label = j; }
        if (used[label]) {
            int l2 = 0; float b2 = used[0] ? 0.f : bin[0];
            for (int j = 1; j < NUM_CLS; j++) {
                float v = used[j] ? 0.f : bin[j];
                if (v > b2) { b2 = v; l2 = j; }
            }
            label = l2;
        }
        if (tot > 0.f) { correct += bin[label]; used[label] = true; }
    }
    out[0] = (float)g_loss;
    out[1] = correct / (float)N_ROWS;

    // reset globals so the next graph replay starts from a clean state
    g_loss = 0.0;
    #pragma unroll
    for (int i = 0; i < NUM_CLS * NUM_CLS; i++) g_counts[i] = 0;
    g_done = 0u;
}

// ---------------- launch ----------------
extern "C" void kernel_launch(void* const* d_in, const int* in_sizes, int n_in,
                              void* d_out, int out_size) {
    const float* x       = (const float*)d_in[0];
    const int*   y32     = (const int*)d_in[1];
    const float* centers = (const float*)d_in[2];

    const int dyn_smem = (int)sizeof(SmemLayout);
    cudaFuncSetAttribute(kmeans_hmma_kernel,
                         cudaFuncAttributeMaxDynamicSharedMemorySize, dyn_smem);

    kmeans_hmma_kernel<<<GRID_X, NTHREADS, dyn_smem>>>(x, y32, centers, (float*)d_out);
}

// round 15
// speedup vs baseline: 1.1405x; 1.0037x over previous
#include <cuda_runtime.h>
#include <cuda_fp16.h>
#include <cstdint>
#include <cfloat>

#define N_ROWS   262144
#define K_CENT   256
#define D_DIM    64
#define NUM_CLS  10
#define TILE_M   128
#define N_TILES  (N_ROWS / TILE_M)   /* 2048 */
#define GRID_X   296                 /* 2 CTAs/SM * 148 SMs */
#define NTHREADS 256

// ---------------- device-global scratch (zero at module load; last CTA re-zeros) --
__device__ double g_loss;                       // = 0.0
__device__ int    g_counts[NUM_CLS * NUM_CLS];  // = {0}
__device__ unsigned int g_done;                 // = 0

// ---------------- helpers ----------------
__device__ __forceinline__ uint32_t h2(float a, float b) {
    __half2 h = __floats2half2_rn(a, b);
    return *reinterpret_cast<uint32_t*>(&h);
}

__device__ __forceinline__ void mma_f16(float& d0, float& d1, float& d2, float& d3,
                                        uint32_t a0, uint32_t a1, uint32_t a2, uint32_t a3,
                                        uint32_t b0, uint32_t b1) {
    asm("mma.sync.aligned.m16n8k16.row.col.f32.f16.f16.f32 "
        "{%0,%1,%2,%3}, {%4,%5,%6,%7}, {%8,%9}, {%0,%1,%2,%3};"
        : "+f"(d0), "+f"(d1), "+f"(d2), "+f"(d3)
        : "r"(a0), "r"(a1), "r"(a2), "r"(a3), "r"(b0), "r"(b1));
}

// minimal e^(-0.1) path: exactly __exp2f(-0.1 * __log2f(e)) = __powf(e, -0.1f),
// but guaranteed 3 instructions (lg2.approx, FMUL, ex2.approx), no wrapper.
__device__ __forceinline__ float pow_m01(float e) {
    float l, w;
    asm("lg2.approx.f32 %0, %1;" : "=f"(l) : "f"(e));
    l = l * -0.1f;
    asm("ex2.approx.f32 %0, %1;" : "=f"(w) : "f"(l));
    return w;
}

// argmin key: truncate e mantissa low bits, pack col into low byte (ties -> lower col)
__device__ __forceinline__ uint32_t akey(float e, int col) {
    return (__float_as_uint(e) & 0xFFFFFF00u) | (uint32_t)col;
}

// k-permutation: within each 16-wide k-chunk, mma slot pairs of thread t4
// ({2t4,2t4+1} and {2t4+8,2t4+9}) hold global elements {4t4..4t4+3}.
// smem: per center n, 8 uint4 units. unit u=(kcp*4+t4)^((n&1)<<2) holds
// B' = -2*c fragments for k-chunks 2*kcp, 2*kcp+1. Conflict-free LDS.128.
struct SmemLayout {
    uint4 B[K_CENT * 8];    // 32 KB
    float c2[K_CENT];       // c2[n] + 1  (the "+1" of 1+d folded in)
};

__global__ __launch_bounds__(NTHREADS, 2)
void kmeans_hmma_kernel(const float* __restrict__ x,
                        const int*   __restrict__ y32,
                        const float* __restrict__ centers,
                        float* __restrict__ out) {
    extern __shared__ unsigned char s_raw[];
    SmemLayout* sm = reinterpret_cast<SmemLayout*>(s_raw);
    __shared__ int    s_hist[NUM_CLS * NUM_CLS];
    __shared__ double s_loss;
    __shared__ int    s_y_is32;
    __shared__ int    s_is_last;

    const int tid  = threadIdx.x;
    const int wid  = tid >> 5;
    const int lane = tid & 31;
    const int g    = lane >> 2;   // row within mma row-group (0..7)
    const int t4   = lane & 3;

    if (tid < NUM_CLS * NUM_CLS) s_hist[tid] = 0;
    if (tid == 0) s_loss = 0.0;
    // label dtype probe: int64 LE -> odd 32-bit words are all 0
    if (wid == 0) {
        int v = (y32[2 * (lane * 7 + 1) + 1] != 0) | (y32[2 * (lane + 64) + 1] != 0);
        uint32_t any = __ballot_sync(0xFFFFFFFFu, v);
        if (lane == 0) s_y_is32 = (any != 0);
    }

    // ---- build fp16 B' = -2*c fragments in smem (permuted k-order), once per CTA --
    for (int w = tid; w < K_CENT * 8; w += NTHREADS) {
        int n   = w >> 3;
        int u8  = w & 7;
        int kcp = u8 >> 2, tt = u8 & 3;
        const float* cn = centers + n * D_DIM;
        float4 v0 = *(const float4*)(cn + kcp * 32 + tt * 4);        // chunk 2kcp
        float4 v1 = *(const float4*)(cn + kcp * 32 + 16 + tt * 4);   // chunk 2kcp+1
        int u = u8 ^ ((n & 1) << 2);
        sm->B[n * 8 + u] = make_uint4(h2(-2.f * v0.x, -2.f * v0.y),
                                      h2(-2.f * v0.z, -2.f * v0.w),
                                      h2(-2.f * v1.x, -2.f * v1.y),
                                      h2(-2.f * v1.z, -2.f * v1.w));
    }
    // center norms + 1 (fp32 exact)
    if (tid < K_CENT) {
        const float4* cp = (const float4*)(centers + tid * D_DIM);
        float a = 0.f;
        #pragma unroll
        for (int j = 0; j < 16; j++) {
            float4 v = cp[j];
            a = fmaf(v.x, v.x, a); a = fmaf(v.y, v.y, a);
            a = fmaf(v.z, v.z, a); a = fmaf(v.w, v.w, a);
        }
        sm->c2[tid] = a + 1.0f;
    }
    __syncthreads();
    const int y_is32 = s_y_is32;

    const uint4* Bbase = sm->B + g * 8;
    const int    uswz  = (g & 1) << 2;
    // hoisted swizzled unit indices (loop-invariant): (0+t4)^uswz and (4+t4)^uswz
    const int u0 = t4 ^ uswz;
    const int u1 = u0 ^ 4;

    float loss_local = 0.f;

    for (int t = blockIdx.x; t < N_TILES; t += GRID_X) {
        const int r0 = t * TILE_M + wid * 16 + g;   // rows r0, r0+8
        const float* xr0 = x + (size_t)r0 * D_DIM + t4 * 4;
        const float* xr1 = xr0 + 8 * D_DIM;

        // ---- fp16 A fragments via ONE float4 per (row, k-chunk) + row norms ----
        uint32_t ah[4][4];
        float x2a = 0.f, x2b = 0.f;
        #pragma unroll
        for (int kc = 0; kc < 4; kc++) {
            float4 va = *(const float4*)(xr0 + kc * 16);
            float4 vb = *(const float4*)(xr1 + kc * 16);
            x2a = fmaf(va.x, va.x, x2a); x2a = fmaf(va.y, va.y, x2a);
            x2a = fmaf(va.z, va.z, x2a); x2a = fmaf(va.w, va.w, x2a);
            x2b = fmaf(vb.x, vb.x, x2b); x2b = fmaf(vb.y, vb.y, x2b);
            x2b = fmaf(vb.z, vb.z, x2b); x2b = fmaf(vb.w, vb.w, x2b);
            ah[kc][0] = h2(va.x, va.y);   // row r0, slots 2t4,2t4+1
            ah[kc][1] = h2(vb.x, vb.y);   // row r1, slots 2t4,2t4+1
            ah[kc][2] = h2(va.z, va.w);   // row r0, slots 2t4+8,2t4+9
            ah[kc][3] = h2(vb.z, vb.w);   // row r1, slots 2t4+8,2t4+9
        }
        x2a += __shfl_xor_sync(0xFFFFFFFFu, x2a, 1);
        x2a += __shfl_xor_sync(0xFFFFFFFFu, x2a, 2);
        x2b += __shfl_xor_sync(0xFFFFFFFFu, x2b, 1);
        x2b += __shfl_xor_sync(0xFFFFFFFFu, x2b, 2);

        float sw0 = 0.f, swe0 = 0.f, sw1 = 0.f, swe1 = 0.f;
        float dmin0 = FLT_MAX, dmin1 = FLT_MAX;
        float dmin10_0 = FLT_MAX, dmin10_1 = FLT_MAX;
        uint32_t key10_0 = 0xFFFFFFFFu, key10_1 = 0xFFFFFFFFu;

        // acc init = (x2 + c2 + 1); B' = -2c  =>  accumulator ends as e = 1 + d
        auto body = [&](int ng, bool track10) {
            const uint4* Bn = Bbase + ng * 64;
            uint4 bv0 = Bn[u0];                  // k-chunks 0,1
            uint4 bv1 = Bn[u1];                  // k-chunks 2,3
            float2 c2p = *(const float2*)(sm->c2 + ng * 8 + t4 * 2);
            float a0 = x2a + c2p.x, a1 = x2a + c2p.y;
            float a2 = x2b + c2p.x, a3 = x2b + c2p.y;
            mma_f16(a0, a1, a2, a3, ah[0][0], ah[0][1], ah[0][2], ah[0][3], bv0.x, bv0.y);
            mma_f16(a0, a1, a2, a3, ah[1][0], ah[1][1], ah[1][2], ah[1][3], bv0.z, bv0.w);
            mma_f16(a0, a1, a2, a3, ah[2][0], ah[2][1], ah[2][2], ah[2][3], bv1.x, bv1.y);
            mma_f16(a0, a1, a2, a3, ah[3][0], ah[3][1], ah[3][2], ah[3][3], bv1.z, bv1.w);
            float w0 = pow_m01(a0);
            float w1 = pow_m01(a1);
            float w2 = pow_m01(a2);
            float w3 = pow_m01(a3);
            sw0 += w0 + w1;
            sw1 += w2 + w3;
            swe0 = fmaf(w0, a0, swe0); swe0 = fmaf(w1, a1, swe0);
            swe1 = fmaf(w2, a2, swe1); swe1 = fmaf(w3, a3, swe1);
            dmin0 = fminf(dmin0, fminf(a0, a1));
            dmin1 = fminf(dmin1, fminf(a2, a3));
            if (track10) {
                // cols < 10 live only in ng=0 (cols 0-7) and ng=1/t4==0 (cols 8,9)
                if (ng == 0 || t4 == 0) {
                    const int cb = ng * 8 + t4 * 2;
                    key10_0 = min(key10_0, min(akey(a0, cb), akey(a1, cb + 1)));
                    key10_1 = min(key10_1, min(akey(a2, cb), akey(a3, cb + 1)));
                    dmin10_0 = fminf(dmin10_0, fminf(a0, a1));
                    dmin10_1 = fminf(dmin10_1, fminf(a2, a3));
                }
            }
        };
        body(0, true);
        body(1, true);
        #pragma unroll 6
        for (int ng = 2; ng < 32; ng++) body(ng, false);

        // quad reduction (4 lanes cover all 256 cols of rows r0, r0+8)
        #pragma unroll
        for (int off = 1; off <= 2; off <<= 1) {
            sw0  += __shfl_xor_sync(0xFFFFFFFFu, sw0,  off);
            swe0 += __shfl_xor_sync(0xFFFFFFFFu, swe0, off);
            sw1  += __shfl_xor_sync(0xFFFFFFFFu, sw1,  off);
            swe1 += __shfl_xor_sync(0xFFFFFFFFu, swe1, off);
            dmin0 = fminf(dmin0, __shfl_xor_sync(0xFFFFFFFFu, dmin0, off));
            dmin1 = fminf(dmin1, __shfl_xor_sync(0xFFFFFFFFu, dmin1, off));
            dmin10_0 = fminf(dmin10_0, __shfl_xor_sync(0xFFFFFFFFu, dmin10_0, off));
            dmin10_1 = fminf(dmin10_1, __shfl_xor_sync(0xFFFFFFFFu, dmin10_1, off));
            key10_0 = min(key10_0, __shfl_xor_sync(0xFFFFFFFFu, key10_0, off));
            key10_1 = min(key10_1, __shfl_xor_sync(0xFFFFFFFFu, key10_1, off));
        }

        if (t4 == 0) {
            loss_local += swe0 / sw0 + swe1 / sw1 - 2.0f;   // swe/sw - 1 per row
            // argmin < 10  <=>  min over cols<10 equals global min (ties -> lower col)
            if (dmin10_0 <= dmin0) {
                int lab = y_is32 ? y32[r0] : y32[2 * r0];
                atomicAdd_block(&s_hist[(int)(key10_0 & 0xFFu) * NUM_CLS + lab], 1);
            }
            if (dmin10_1 <= dmin1) {
                int r1 = r0 + 8;
                int lab = y_is32 ? y32[r1] : y32[2 * r1];
                atomicAdd_block(&s_hist[(int)(key10_1 & 0xFFu) * NUM_CLS + lab], 1);
            }
        }
    }

    // ---- flush per-CTA accumulators to global ----
    #pragma unroll
    for (int off = 16; off > 0; off >>= 1)
        loss_local += __shfl_xor_sync(0xFFFFFFFFu, loss_local, off);
    if (lane == 0) atomicAdd_block(&s_loss, (double)loss_local);
    __syncthreads();
    if (tid == 0) atomicAdd(&g_loss, s_loss);
    if (tid < NUM_CLS * NUM_CLS && s_hist[tid] > 0)
        atomicAdd(&g_counts[tid], s_hist[tid]);

    // ---- last-CTA fused finalize ----
    __threadfence();
    __syncthreads();
    if (tid == 0) {
        unsigned int prev = atomicAdd(&g_done, 1u);
        s_is_last = (prev == GRID_X - 1);
    }
    __syncthreads();
    if (!s_is_last || tid != 0) return;

    float counts[NUM_CLS * NUM_CLS];
    #pragma unroll
    for (int i = 0; i < NUM_CLS * NUM_CLS; i++)
        counts[i] = (float)atomicAdd(&g_counts[i], 0);

    bool used[NUM_CLS];
    #pragma unroll
    for (int i = 0; i < NUM_CLS; i++) used[i] = false;

    float correct = 0.f;
    for (int i = 0; i < NUM_CLS; i++) {
        const float* bin = &counts[i * NUM_CLS];
        float tot = 0.f;
        for (int j = 0; j < NUM_CLS; j++) tot += bin[j];
        int label = 0; float best = bin[0];
        for (int j = 1; j < NUM_CLS; j++)
            if (bin[j] > best) { best = bin[j]; label = j; }
        if (used[label]) {
            int l2 = 0; float b2 = used[0] ? 0.f : bin[0];
            for (int j = 1; j < NUM_CLS; j++) {
                float v = used[j] ? 0.f : bin[j];
                if (v > b2) { b2 = v; l2 = j; }
            }
            label = l2;
        }
        if (tot > 0.f) { correct += bin[label]; used[label] = true; }
    }
    out[0] = (float)g_loss;
    out[1] = correct / (float)N_ROWS;

    // reset globals so the next graph replay starts from a clean state
    g_loss = 0.0;
    #pragma unroll
    for (int i = 0; i < NUM_CLS * NUM_CLS; i++) g_counts[i] = 0;
    g_done = 0u;
}

// ---------------- launch ----------------
extern "C" void kernel_launch(void* const* d_in, const int* in_sizes, int n_in,
                              void* d_out, int out_size) {
    const float* x       = (const float*)d_in[0];
    const int*   y32     = (const int*)d_in[1];
    const float* centers = (const float*)d_in[2];

    const int dyn_smem = (int)sizeof(SmemLayout);
    cudaFuncSetAttribute(kmeans_hmma_kernel,
                         cudaFuncAttributeMaxDynamicSharedMemorySize, dyn_smem);

    kmeans_hmma_kernel<<<GRID_X, NTHREADS, dyn_smem>>>(x, y32, centers, (float*)d_out);
}

// round 17
// speedup vs baseline: 1.1809x; 1.0354x over previous
#include <cuda_runtime.h>
#include <cuda_fp16.h>
#include <cstdint>
#include <cfloat>

#define N_ROWS   262144
#define K_CENT   256
#define D_DIM    64
#define NUM_CLS  10
#define TILE_M   128
#define N_TILES  (N_ROWS / TILE_M)   /* 2048 */
#define GRID_X   296                 /* 2 CTAs/SM * 148 SMs */
#define NTHREADS 256

// ---------------- device-global scratch (zero at module load; last CTA re-zeros) --
__device__ double g_loss;                       // = 0.0
__device__ int    g_counts[NUM_CLS * NUM_CLS];  // = {0}
__device__ unsigned int g_done;                 // = 0

// ---------------- helpers ----------------
__device__ __forceinline__ uint32_t h2(float a, float b) {
    __half2 h = __floats2half2_rn(a, b);
    return *reinterpret_cast<uint32_t*>(&h);
}

__device__ __forceinline__ void mma_f16(float& d0, float& d1, float& d2, float& d3,
                                        uint32_t a0, uint32_t a1, uint32_t a2, uint32_t a3,
                                        uint32_t b0, uint32_t b1) {
    asm("mma.sync.aligned.m16n8k16.row.col.f32.f16.f16.f32 "
        "{%0,%1,%2,%3}, {%4,%5,%6,%7}, {%8,%9}, {%0,%1,%2,%3};"
        : "+f"(d0), "+f"(d1), "+f"(d2), "+f"(d3)
        : "r"(a0), "r"(a1), "r"(a2), "r"(a3), "r"(b0), "r"(b1));
}

// minimal e^(-0.1): exactly __exp2f(-0.1 * __log2f(e)) = __powf(e, -0.1f)
__device__ __forceinline__ float pow_m01(float e) {
    float l, w;
    asm("lg2.approx.f32 %0, %1;" : "=f"(l) : "f"(e));
    l = l * -0.1f;
    asm("ex2.approx.f32 %0, %1;" : "=f"(w) : "f"(l));
    return w;
}

// argmin key: truncate e mantissa low bits, pack col into low byte (ties -> lower col)
__device__ __forceinline__ uint32_t akey(float e, int col) {
    return (__float_as_uint(e) & 0xFFFFFF00u) | (uint32_t)col;
}

// k-permutation: within each 16-wide k-chunk, mma slot pairs of thread t4
// ({2t4,2t4+1} and {2t4+8,2t4+9}) hold global elements {4t4..4t4+3}.
// smem: per center n, 8 uint4 units. unit u=(kcp*4+t4)^((n&1)<<2) holds
// B' = -2*c fragments for k-chunks 2*kcp, 2*kcp+1. Conflict-free LDS.128.
struct SmemLayout {
    uint4 B[K_CENT * 8];    // 32 KB
    float c2[K_CENT];       // c2[n] + 1  (the "+1" of 1+d folded in)
};

__global__ __launch_bounds__(NTHREADS, 2)
void kmeans_hmma_kernel(const float* __restrict__ x,
                        const int*   __restrict__ y32,
                        const float* __restrict__ centers,
                        float* __restrict__ out) {
    extern __shared__ unsigned char s_raw[];
    SmemLayout* sm = reinterpret_cast<SmemLayout*>(s_raw);
    __shared__ int    s_hist[NUM_CLS * NUM_CLS];
    __shared__ float  s_cnt[NUM_CLS * NUM_CLS];
    __shared__ double s_loss;
    __shared__ int    s_y_is32;
    __shared__ int    s_is_last;

    const int tid  = threadIdx.x;
    const int wid  = tid >> 5;
    const int lane = tid & 31;
    const int g    = lane >> 2;   // row within mma row-group (0..7)
    const int t4   = lane & 3;

    if (tid < NUM_CLS * NUM_CLS) s_hist[tid] = 0;
    if (tid == 0) s_loss = 0.0;
    // label dtype probe: int64 LE -> odd 32-bit words are all 0
    if (wid == 0) {
        int v = (y32[2 * (lane * 7 + 1) + 1] != 0) | (y32[2 * (lane + 64) + 1] != 0);
        uint32_t any = __ballot_sync(0xFFFFFFFFu, v);
        if (lane == 0) s_y_is32 = (any != 0);
    }

    // ---- build fp16 B' = -2*c fragments in smem (permuted k-order), once per CTA --
    for (int w = tid; w < K_CENT * 8; w += NTHREADS) {
        int n   = w >> 3;
        int u8  = w & 7;
        int kcp = u8 >> 2, tt = u8 & 3;
        const float* cn = centers + n * D_DIM;
        float4 v0 = *(const float4*)(cn + kcp * 32 + tt * 4);        // chunk 2kcp
        float4 v1 = *(const float4*)(cn + kcp * 32 + 16 + tt * 4);   // chunk 2kcp+1
        int u = u8 ^ ((n & 1) << 2);
        sm->B[n * 8 + u] = make_uint4(h2(-2.f * v0.x, -2.f * v0.y),
                                      h2(-2.f * v0.z, -2.f * v0.w),
                                      h2(-2.f * v1.x, -2.f * v1.y),
                                      h2(-2.f * v1.z, -2.f * v1.w));
    }
    // center norms + 1 (fp32 exact)
    if (tid < K_CENT) {
        const float4* cp = (const float4*)(centers + tid * D_DIM);
        float a = 0.f;
        #pragma unroll
        for (int j = 0; j < 16; j++) {
            float4 v = cp[j];
            a = fmaf(v.x, v.x, a); a = fmaf(v.y, v.y, a);
            a = fmaf(v.z, v.z, a); a = fmaf(v.w, v.w, a);
        }
        sm->c2[tid] = a + 1.0f;
    }
    __syncthreads();
    const int y_is32 = s_y_is32;

    const uint4* Bbase = sm->B + g * 8;
    const int    uswz  = (g & 1) << 2;
    // hoisted swizzled unit indices (loop-invariant): (0+t4)^uswz and (4+t4)^uswz
    const int u0 = t4 ^ uswz;
    const int u1 = u0 ^ 4;

    float loss_local = 0.f;

    for (int t = blockIdx.x; t < N_TILES; t += GRID_X) {
        const int r0 = t * TILE_M + wid * 16 + g;   // rows r0, r0+8
        const float* xr0 = x + (size_t)r0 * D_DIM + t4 * 4;
        const float* xr1 = xr0 + 8 * D_DIM;

        // ---- fp16 A fragments via ONE float4 per (row, k-chunk) + row norms ----
        uint32_t ah[4][4];
        float x2a = 0.f, x2b = 0.f;
        #pragma unroll
        for (int kc = 0; kc < 4; kc++) {
            float4 va = *(const float4*)(xr0 + kc * 16);
            float4 vb = *(const float4*)(xr1 + kc * 16);
            x2a = fmaf(va.x, va.x, x2a); x2a = fmaf(va.y, va.y, x2a);
            x2a = fmaf(va.z, va.z, x2a); x2a = fmaf(va.w, va.w, x2a);
            x2b = fmaf(vb.x, vb.x, x2b); x2b = fmaf(vb.y, vb.y, x2b);
            x2b = fmaf(vb.z, vb.z, x2b); x2b = fmaf(vb.w, vb.w, x2b);
            ah[kc][0] = h2(va.x, va.y);   // row r0, slots 2t4,2t4+1
            ah[kc][1] = h2(vb.x, vb.y);   // row r1, slots 2t4,2t4+1
            ah[kc][2] = h2(va.z, va.w);   // row r0, slots 2t4+8,2t4+9
            ah[kc][3] = h2(vb.z, vb.w);   // row r1, slots 2t4+8,2t4+9
        }
        x2a += __shfl_xor_sync(0xFFFFFFFFu, x2a, 1);
        x2a += __shfl_xor_sync(0xFFFFFFFFu, x2a, 2);
        x2b += __shfl_xor_sync(0xFFFFFFFFu, x2b, 1);
        x2b += __shfl_xor_sync(0xFFFFFFFFu, x2b, 2);

        float sw0 = 0.f, swe0 = 0.f, sw1 = 0.f, swe1 = 0.f;
        float dmin0 = FLT_MAX, dmin1 = FLT_MAX;
        float dmin10_0 = FLT_MAX, dmin10_1 = FLT_MAX;
        uint32_t key10_0 = 0xFFFFFFFFu, key10_1 = 0xFFFFFFFFu;

        // acc init = (x2 + c2 + 1); B' = -2c  =>  accumulator ends as e = 1 + d
        auto body = [&](int ng, bool track10) {
            const uint4* Bn = Bbase + ng * 64;
            uint4 bv0 = Bn[u0];                  // k-chunks 0,1
            uint4 bv1 = Bn[u1];                  // k-chunks 2,3
            float2 c2p = *(const float2*)(sm->c2 + ng * 8 + t4 * 2);
            float a0 = x2a + c2p.x, a1 = x2a + c2p.y;
            float a2 = x2b + c2p.x, a3 = x2b + c2p.y;
            mma_f16(a0, a1, a2, a3, ah[0][0], ah[0][1], ah[0][2], ah[0][3], bv0.x, bv0.y);
            mma_f16(a0, a1, a2, a3, ah[1][0], ah[1][1], ah[1][2], ah[1][3], bv0.z, bv0.w);
            mma_f16(a0, a1, a2, a3, ah[2][0], ah[2][1], ah[2][2], ah[2][3], bv1.x, bv1.y);
            mma_f16(a0, a1, a2, a3, ah[3][0], ah[3][1], ah[3][2], ah[3][3], bv1.z, bv1.w);
            float w0 = pow_m01(a0);
            float w1 = pow_m01(a1);
            float w2 = pow_m01(a2);
            float w3 = pow_m01(a3);
            sw0 += w0 + w1;
            sw1 += w2 + w3;
            swe0 = fmaf(w0, a0, swe0); swe0 = fmaf(w1, a1, swe0);
            swe1 = fmaf(w2, a2, swe1); swe1 = fmaf(w3, a3, swe1);
            dmin0 = fminf(dmin0, fminf(a0, a1));
            dmin1 = fminf(dmin1, fminf(a2, a3));
            if (track10) {
                // cols < 10 live only in ng=0 (cols 0-7) and ng=1/t4==0 (cols 8,9)
                if (ng == 0 || t4 == 0) {
                    const int cb = ng * 8 + t4 * 2;
                    key10_0 = min(key10_0, min(akey(a0, cb), akey(a1, cb + 1)));
                    key10_1 = min(key10_1, min(akey(a2, cb), akey(a3, cb + 1)));
                    dmin10_0 = fminf(dmin10_0, fminf(a0, a1));
                    dmin10_1 = fminf(dmin10_1, fminf(a2, a3));
                }
            }
        };
        body(0, true);
        body(1, true);
        #pragma unroll 6
        for (int ng = 2; ng < 32; ng++) body(ng, false);

        // quad reduction (4 lanes cover all 256 cols of rows r0, r0+8)
        #pragma unroll
        for (int off = 1; off <= 2; off <<= 1) {
            sw0  += __shfl_xor_sync(0xFFFFFFFFu, sw0,  off);
            swe0 += __shfl_xor_sync(0xFFFFFFFFu, swe0, off);
            sw1  += __shfl_xor_sync(0xFFFFFFFFu, sw1,  off);
            swe1 += __shfl_xor_sync(0xFFFFFFFFu, swe1, off);
            dmin0 = fminf(dmin0, __shfl_xor_sync(0xFFFFFFFFu, dmin0, off));
            dmin1 = fminf(dmin1, __shfl_xor_sync(0xFFFFFFFFu, dmin1, off));
            dmin10_0 = fminf(dmin10_0, __shfl_xor_sync(0xFFFFFFFFu, dmin10_0, off));
            dmin10_1 = fminf(dmin10_1, __shfl_xor_sync(0xFFFFFFFFu, dmin10_1, off));
            key10_0 = min(key10_0, __shfl_xor_sync(0xFFFFFFFFu, key10_0, off));
            key10_1 = min(key10_1, __shfl_xor_sync(0xFFFFFFFFu, key10_1, off));
        }

        if (t4 == 0) {
            loss_local += swe0 / sw0 + swe1 / sw1 - 2.0f;   // swe/sw - 1 per row
            // argmin < 10  <=>  min over cols<10 equals global min (ties -> lower col)
            if (dmin10_0 <= dmin0) {
                int lab = y_is32 ? y32[r0] : y32[2 * r0];
                atomicAdd_block(&s_hist[(int)(key10_0 & 0xFFu) * NUM_CLS + lab], 1);
            }
            if (dmin10_1 <= dmin1) {
                int r1 = r0 + 8;
                int lab = y_is32 ? y32[r1] : y32[2 * r1];
                atomicAdd_block(&s_hist[(int)(key10_1 & 0xFFu) * NUM_CLS + lab], 1);
            }
        }
    }

    // ---- flush per-CTA accumulators to global ----
    #pragma unroll
    for (int off = 16; off > 0; off >>= 1)
        loss_local += __shfl_xor_sync(0xFFFFFFFFu, loss_local, off);
    if (lane == 0) atomicAdd_block(&s_loss, (double)loss_local);
    __syncthreads();
    if (tid == 0) atomicAdd(&g_loss, s_loss);
    if (tid < NUM_CLS * NUM_CLS && s_hist[tid] > 0)
        atomicAdd(&g_counts[tid], s_hist[tid]);

    // ---- last-CTA fused finalize ----
    __threadfence();
    __syncthreads();
    if (tid == 0) {
        unsigned int prev = atomicAdd(&g_done, 1u);
        s_is_last = (prev == GRID_X - 1);
    }
    __syncthreads();
    if (!s_is_last) return;

    // parallel fetch of all counts (MLP ~100 instead of a serial dependent chain)
    if (tid < NUM_CLS * NUM_CLS)
        s_cnt[tid] = (float)atomicAdd(&g_counts[tid], 0);
    __syncthreads();
    if (tid != 0) return;

    bool used[NUM_CLS];
    #pragma unroll
    for (int i = 0; i < NUM_CLS; i++) used[i] = false;

    float correct = 0.f;
    for (int i = 0; i < NUM_CLS; i++) {
        const float* bin = &s_cnt[i * NUM_CLS];
        float tot = 0.f;
        for (int j = 0; j < NUM_CLS; j++) tot += bin[j];
        int label = 0; float best = bin[0];
        for (int j = 1; j < NUM_CLS; j++)
            if (bin[j] > best) { best = bin[j]; label = j; }
        if (used[label]) {
            int l2 = 0; float b2 = used[0] ? 0.f : bin[0];
            for (int j = 1; j < NUM_CLS; j++) {
                float v = used[j] ? 0.f : bin[j];
                if (v > b2) { b2 = v; l2 = j; }
            }
            label = l2;
        }
        if (tot > 0.f) { correct += bin[label]; used[label] = true; }
    }
    out[0] = (float)g_loss;
    out[1] = correct / (float)N_ROWS;

    // reset globals so the next graph replay starts from a clean state
    g_loss = 0.0;
    #pragma unroll
    for (int i = 0; i < NUM_CLS * NUM_CLS; i++) g_counts[i] = 0;
    g_done = 0u;
}

// ---------------- launch ----------------
extern "C" void kernel_launch(void* const* d_in, const int* in_sizes, int n_in,
                              void* d_out, int out_size) {
    const float* x       = (const float*)d_in[0];
    const int*   y32     = (const int*)d_in[1];
    const float* centers = (const float*)d_in[2];

    const int dyn_smem = (int)sizeof(SmemLayout);
    cudaFuncSetAttribute(kmeans_hmma_kernel,
                         cudaFuncAttributeMaxDynamicSharedMemorySize, dyn_smem);

    kmeans_hmma_kernel<<<GRID_X, NTHREADS, dyn_smem>>>(x, y32, centers, (float*)d_out);
}